// round 3
// baseline (speedup 1.0000x reference)
#include <cuda_runtime.h>
#include <math.h>

#define Bsz 2
#define Tsz 2048
#define Csz 1024
#define Hn  16
#define HDd 64

// Scratch (static device arrays — allocation-free per harness rules)
__device__ float g_qkv[Bsz * Tsz * 3 * Csz];      // [B*T, 3C]
__device__ float g_q[Bsz * Hn * Tsz * HDd];       // [B,H,T,HD] rope'd
__device__ float g_k[Bsz * Hn * Tsz * HDd];
__device__ float g_v[Bsz * Hn * Tsz * HDd];
__device__ float g_y[Bsz * Tsz * Csz];            // [B,T,C] attention out

// ---------------------------------------------------------------------------
// SGEMM: C[M,N] = A[M,K] @ B[K,N] + bias[N]
// 128x128 block tile, BK=16, 256 threads, 8x8 register micro-tile.
// ---------------------------------------------------------------------------
__global__ __launch_bounds__(256, 2)
void sgemm128(const float* __restrict__ A,
              const float* __restrict__ Bm,
              const float* __restrict__ bias,
              float* __restrict__ Cm,
              int M, int N, int K) {
    __shared__ float As[16][132];   // A tile transposed: As[k][m]
    __shared__ float Bs[16][132];   // B tile natural:    Bs[k][n] (128 used)

    const int tid = threadIdx.x;
    const int tx = tid & 15;
    const int ty = tid >> 4;
    const int m0 = blockIdx.y * 128;
    const int n0 = blockIdx.x * 128;

    float acc[8][8] = {};

    for (int k0 = 0; k0 < K; k0 += 16) {
        #pragma unroll
        for (int i = 0; i < 2; i++) {
            const int idx = tid + i * 256;
            const int row = idx >> 2;
            const int c4  = idx & 3;
            float4 a = *(const float4*)&A[(size_t)(m0 + row) * K + k0 + c4 * 4];
            As[c4 * 4 + 0][row] = a.x;
            As[c4 * 4 + 1][row] = a.y;
            As[c4 * 4 + 2][row] = a.z;
            As[c4 * 4 + 3][row] = a.w;
        }
        #pragma unroll
        for (int i = 0; i < 2; i++) {
            const int idx = tid + i * 256;
            const int br  = idx >> 5;
            const int bc4 = idx & 31;
            *(float4*)&Bs[br][bc4 * 4] =
                *(const float4*)&Bm[(size_t)(k0 + br) * N + n0 + bc4 * 4];
        }
        __syncthreads();

        #pragma unroll
        for (int kk = 0; kk < 16; kk++) {
            float av[8], bv[8];
            float4 a0 = *(const float4*)&As[kk][ty * 8];
            float4 a1 = *(const float4*)&As[kk][ty * 8 + 4];
            float4 b0 = *(const float4*)&Bs[kk][tx * 8];
            float4 b1 = *(const float4*)&Bs[kk][tx * 8 + 4];
            av[0]=a0.x; av[1]=a0.y; av[2]=a0.z; av[3]=a0.w;
            av[4]=a1.x; av[5]=a1.y; av[6]=a1.z; av[7]=a1.w;
            bv[0]=b0.x; bv[1]=b0.y; bv[2]=b0.z; bv[3]=b0.w;
            bv[4]=b1.x; bv[5]=b1.y; bv[6]=b1.z; bv[7]=b1.w;
            #pragma unroll
            for (int i = 0; i < 8; i++)
                #pragma unroll
                for (int j = 0; j < 8; j++)
                    acc[i][j] += av[i] * bv[j];
        }
        __syncthreads();
    }

    float4 bb0 = *(const float4*)&bias[n0 + tx * 8];
    float4 bb1 = *(const float4*)&bias[n0 + tx * 8 + 4];
    float bv[8] = {bb0.x, bb0.y, bb0.z, bb0.w, bb1.x, bb1.y, bb1.z, bb1.w};
    #pragma unroll
    for (int i = 0; i < 8; i++) {
        float4 o0, o1;
        o0.x = acc[i][0] + bv[0]; o0.y = acc[i][1] + bv[1];
        o0.z = acc[i][2] + bv[2]; o0.w = acc[i][3] + bv[3];
        o1.x = acc[i][4] + bv[4]; o1.y = acc[i][5] + bv[5];
        o1.z = acc[i][6] + bv[6]; o1.w = acc[i][7] + bv[7];
        float* cp = &Cm[(size_t)(m0 + ty * 8 + i) * N + n0 + tx * 8];
        *(float4*)cp = o0;
        *(float4*)(cp + 4) = o1;
    }
}

// ---------------------------------------------------------------------------
// RoPE + split + transpose: g_qkv[B*T,3C] -> g_q/g_k (rope'd), g_v  [B,H,T,HD]
// ---------------------------------------------------------------------------
__global__ void rope_split_kernel(const float* __restrict__ qkv) {
    const int idx = blockIdx.x * blockDim.x + threadIdx.x;
    const int d2 = idx & 31;
    const int h  = (idx >> 5) & 15;
    const int t  = (idx >> 9) & 2047;
    const int b  = idx >> 20;

    const float* base = qkv + (size_t)(b * Tsz + t) * (3 * Csz);
    const int off = h * HDd + d2;

    const float qf = base[off],           qs = base[off + 32];
    const float kf = base[Csz + off],     ks = base[Csz + off + 32];
    const float vf = base[2 * Csz + off], vs = base[2 * Csz + off + 32];

    const float inv_ts = powf(10000.0f, -(float)d2 * (1.0f / 32.0f));
    const float ang = (float)t * inv_ts;
    float sn, cs;
    sincosf(ang, &sn, &cs);

    const size_t o = (size_t)((b * Hn + h) * Tsz + t) * HDd + d2;
    g_q[o]      = qf * cs - qs * sn;
    g_q[o + 32] = qs * cs + qf * sn;
    g_k[o]      = kf * cs - ks * sn;
    g_k[o + 32] = ks * cs + kf * sn;
    g_v[o]      = vf;
    g_v[o + 32] = vs;
}

// ---------------------------------------------------------------------------
// Flash attention v2 (fp32, online softmax, causal).
// Q tile = 128 rows, K/V tile = 64. 256 threads (16 col-groups x 16 row-groups),
// micro-tile 8 rows x 4 cols. All smem traffic is conflict-free float4:
//   Qs natural (broadcast reads), Ks natural + XOR swizzle (strided row reads),
//   Vs natural, Ps natural (float4 stores, broadcast float4 reads).
// ---------------------------------------------------------------------------
__global__ __launch_bounds__(256, 2)
void flash_attn128(const float* __restrict__ Q,
                   const float* __restrict__ K,
                   const float* __restrict__ V,
                   float* __restrict__ Y) {
    extern __shared__ float sm[];
    float* Qs = sm;           // [128][64]
    float* Ks = sm + 8192;    // [64][64], slot-swizzled
    float* Vs = sm + 12288;   // [64][64]
    float* Ps = sm + 16384;   // [128][64]

    const int tid = threadIdx.x;
    const int tx = tid & 15;          // column group (4 cols / head dims)
    const int ty = tid >> 4;          // row group (8 q-rows)
    const int qt = gridDim.x - 1 - blockIdx.x;   // long blocks first
    const int h  = blockIdx.y;
    const int b  = blockIdx.z;
    const size_t bh = (size_t)(b * Hn + h) * Tsz;
    const int rbase = ty * 8;
    const int cbase = tx * 4;

    // Load Q tile (natural layout, coalesced)
    #pragma unroll
    for (int i = 0; i < 8; i++) {
        const int idx = tid + i * 256;      // 0..2047
        const int r  = idx >> 4;            // 0..127
        const int d4 = idx & 15;
        *(float4*)&Qs[r * 64 + d4 * 4] =
            *(const float4*)&Q[(bh + qt * 128 + r) * HDd + d4 * 4];
    }

    float m[8], l[8], acc[8][4];
    #pragma unroll
    for (int i = 0; i < 8; i++) {
        m[i] = -1e30f; l[i] = 0.0f;
        acc[i][0] = acc[i][1] = acc[i][2] = acc[i][3] = 0.0f;
    }

    const int nkt = 2 * qt + 2;
    for (int kt = 0; kt < nkt; kt++) {
        __syncthreads();   // prior GEMM2 readers of Ks/Vs done; Qs visible
        // Load K (swizzled) + V (natural)
        #pragma unroll
        for (int i = 0; i < 4; i++) {
            const int idx = tid + i * 256;  // 0..1023
            const int r  = idx >> 4;        // 0..63
            const int d4 = idx & 15;
            float4 kk = *(const float4*)&K[(bh + kt * 64 + r) * HDd + d4 * 4];
            const int slot = d4 ^ ((r >> 2) & 15);
            *(float4*)&Ks[r * 64 + slot * 4] = kk;
            *(float4*)&Vs[r * 64 + d4 * 4] =
                *(const float4*)&V[(bh + kt * 64 + r) * HDd + d4 * 4];
        }
        __syncthreads();

        // GEMM1: s[i][j] = sum_d Q[rbase+i][d] * K[cbase+j][d]
        float s[8][4] = {};
        #pragma unroll
        for (int c4 = 0; c4 < 16; c4++) {
            float4 kv[4];
            const int slot4 = (c4 ^ tx) * 4;   // (cbase+j)>>2 == tx for j<4
            #pragma unroll
            for (int j = 0; j < 4; j++)
                kv[j] = *(const float4*)&Ks[(cbase + j) * 64 + slot4];
            #pragma unroll
            for (int i = 0; i < 8; i++) {
                float4 q = *(const float4*)&Qs[(rbase + i) * 64 + c4 * 4];
                #pragma unroll
                for (int j = 0; j < 4; j++) {
                    s[i][j] += q.x * kv[j].x;
                    s[i][j] += q.y * kv[j].y;
                    s[i][j] += q.z * kv[j].z;
                    s[i][j] += q.w * kv[j].w;
                }
            }
        }

        // Scale + causal mask (only the last two K tiles can be masked)
        const bool dotest = (kt >= 2 * qt);
        #pragma unroll
        for (int i = 0; i < 8; i++)
            #pragma unroll
            for (int j = 0; j < 4; j++) {
                float sv = s[i][j] * 0.125f;
                if (dotest &&
                    (kt * 64 + cbase + j) > (qt * 128 + rbase + i))
                    sv = -1e30f;
                s[i][j] = sv;
            }

        // Online softmax per row (reduction across the 16 tx lanes)
        #pragma unroll
        for (int i = 0; i < 8; i++) {
            float tm = fmaxf(fmaxf(s[i][0], s[i][1]), fmaxf(s[i][2], s[i][3]));
            tm = fmaxf(tm, __shfl_xor_sync(0xffffffffu, tm, 1));
            tm = fmaxf(tm, __shfl_xor_sync(0xffffffffu, tm, 2));
            tm = fmaxf(tm, __shfl_xor_sync(0xffffffffu, tm, 4));
            tm = fmaxf(tm, __shfl_xor_sync(0xffffffffu, tm, 8));
            const float mn = fmaxf(m[i], tm);
            const float corr = __expf(m[i] - mn);
            float4 pp;
            pp.x = __expf(s[i][0] - mn);
            pp.y = __expf(s[i][1] - mn);
            pp.z = __expf(s[i][2] - mn);
            pp.w = __expf(s[i][3] - mn);
            *(float4*)&Ps[(rbase + i) * 64 + cbase] = pp;
            float sum = (pp.x + pp.y) + (pp.z + pp.w);
            sum += __shfl_xor_sync(0xffffffffu, sum, 1);
            sum += __shfl_xor_sync(0xffffffffu, sum, 2);
            sum += __shfl_xor_sync(0xffffffffu, sum, 4);
            sum += __shfl_xor_sync(0xffffffffu, sum, 8);
            l[i] = l[i] * corr + sum;
            m[i] = mn;
            acc[i][0] *= corr; acc[i][1] *= corr;
            acc[i][2] *= corr; acc[i][3] *= corr;
        }
        __syncwarp();   // P rows are warp-private: stores visible to readers

        // GEMM2: acc[i][j] += sum_kk P[rbase+i][kk] * V[kk][cbase+j]
        #pragma unroll
        for (int c4 = 0; c4 < 16; c4++) {
            float4 v4[4];
            #pragma unroll
            for (int kkj = 0; kkj < 4; kkj++)
                v4[kkj] = *(const float4*)&Vs[(c4 * 4 + kkj) * 64 + cbase];
            #pragma unroll
            for (int i = 0; i < 8; i++) {
                float4 p = *(const float4*)&Ps[(rbase + i) * 64 + c4 * 4];
                acc[i][0] += p.x * v4[0].x; acc[i][0] += p.y * v4[1].x;
                acc[i][0] += p.z * v4[2].x; acc[i][0] += p.w * v4[3].x;
                acc[i][1] += p.x * v4[0].y; acc[i][1] += p.y * v4[1].y;
                acc[i][1] += p.z * v4[2].y; acc[i][1] += p.w * v4[3].y;
                acc[i][2] += p.x * v4[0].z; acc[i][2] += p.y * v4[1].z;
                acc[i][2] += p.z * v4[2].z; acc[i][2] += p.w * v4[3].z;
                acc[i][3] += p.x * v4[0].w; acc[i][3] += p.y * v4[1].w;
                acc[i][3] += p.z * v4[2].w; acc[i][3] += p.w * v4[3].w;
            }
        }
    }

    // Epilogue: normalize and write out (interleave heads back to [B,T,C])
    #pragma unroll
    for (int i = 0; i < 8; i++) {
        const float inv = 1.0f / l[i];
        float4 o;
        o.x = acc[i][0] * inv; o.y = acc[i][1] * inv;
        o.z = acc[i][2] * inv; o.w = acc[i][3] * inv;
        const size_t yoff =
            ((size_t)(b * Tsz) + qt * 128 + rbase + i) * Csz + h * HDd + cbase;
        *(float4*)&Y[yoff] = o;
    }
}

// ---------------------------------------------------------------------------
extern "C" void kernel_launch(void* const* d_in, const int* in_sizes, int n_in,
                              void* d_out, int out_size) {
    (void)in_sizes; (void)n_in; (void)out_size;
    const float* x      = (const float*)d_in[0];
    const float* w_attn = (const float*)d_in[1];
    const float* b_attn = (const float*)d_in[2];
    const float* w_proj = (const float*)d_in[3];
    const float* b_proj = (const float*)d_in[4];
    float* out = (float*)d_out;

    float *p_qkv, *p_q, *p_k, *p_v, *p_y;
    cudaGetSymbolAddress((void**)&p_qkv, g_qkv);
    cudaGetSymbolAddress((void**)&p_q,   g_q);
    cudaGetSymbolAddress((void**)&p_k,   g_k);
    cudaGetSymbolAddress((void**)&p_v,   g_v);
    cudaGetSymbolAddress((void**)&p_y,   g_y);

    const int M = Bsz * Tsz;  // 4096

    // 1) QKV = x @ w_attn + b_attn   [4096, 3072]
    sgemm128<<<dim3(3 * Csz / 128, M / 128), 256>>>(
        x, w_attn, b_attn, p_qkv, M, 3 * Csz, Csz);

    // 2) RoPE + split + transpose
    rope_split_kernel<<<(Bsz * Tsz * Hn * 32) / 256, 256>>>(p_qkv);

    // 3) Flash attention (Q tile 128, KV tile 64)
    const int smem_bytes = 24576 * sizeof(float);  // 96 KB
    cudaFuncSetAttribute(flash_attn128,
                         cudaFuncAttributeMaxDynamicSharedMemorySize, smem_bytes);
    flash_attn128<<<dim3(Tsz / 128, Hn, Bsz), 256, smem_bytes>>>(
        p_q, p_k, p_v, p_y);

    // 4) out = y @ w_proj + b_proj   [4096, 1024]
    sgemm128<<<dim3(Csz / 128, M / 128), 256>>>(
        p_y, w_proj, b_proj, out, M, Csz, Csz);
}

// round 5
// speedup vs baseline: 1.5584x; 1.5584x over previous
#include <cuda_runtime.h>
#include <cuda_fp16.h>
#include <math.h>
#include <stdint.h>

#define Bsz 2
#define Tsz 2048
#define Csz 1024
#define Hn  16
#define HDd 64

// Scratch
__device__ float g_qkv[Bsz * Tsz * 3 * Csz];
__device__ float g_q[Bsz * Hn * Tsz * HDd];
__device__ float g_k[Bsz * Hn * Tsz * HDd];
__device__ float g_v[Bsz * Hn * Tsz * HDd];
__device__ float g_y[Bsz * Tsz * Csz];

// ===========================================================================
// Helpers
// ===========================================================================
__device__ __forceinline__ uint32_t smem_u32(const void* p) {
    uint32_t a;
    asm("{ .reg .u64 t; cvta.to.shared.u64 t, %1; cvt.u32.u64 %0, t; }"
        : "=r"(a) : "l"(p));
    return a;
}

#define LDSM4(r0, r1, r2, r3, ad)                                              \
    asm volatile("ldmatrix.sync.aligned.m8n8.x4.shared.b16 {%0,%1,%2,%3}, [%4];" \
                 : "=r"(r0), "=r"(r1), "=r"(r2), "=r"(r3) : "r"(ad))

#define LDSM4T(r0, r1, r2, r3, ad)                                             \
    asm volatile("ldmatrix.sync.aligned.m8n8.x4.trans.shared.b16 {%0,%1,%2,%3}, [%4];" \
                 : "=r"(r0), "=r"(r1), "=r"(r2), "=r"(r3) : "r"(ad))

#define MMA16816(d, a, b0, b1)                                                 \
    asm volatile("mma.sync.aligned.m16n8k16.row.col.f32.f16.f16.f32 "          \
                 "{%0,%1,%2,%3}, {%4,%5,%6,%7}, {%8,%9}, {%0,%1,%2,%3};"       \
                 : "+f"((d)[0]), "+f"((d)[1]), "+f"((d)[2]), "+f"((d)[3])      \
                 : "r"((a)[0]), "r"((a)[1]), "r"((a)[2]), "r"((a)[3]),         \
                   "r"(b0), "r"(b1))

__device__ __forceinline__ float ex2f(float x) {
    float y;
    asm("ex2.approx.f32 %0, %1;" : "=f"(y) : "f"(x));
    return y;
}
__device__ __forceinline__ uint32_t packh2(float hi, float lo) {
    uint32_t r;
    asm("cvt.rn.f16x2.f32 %0, %1, %2;" : "=r"(r) : "f"(hi), "f"(lo));
    return r;
}

// Store float4 (4 fp32) as 4 fp16 (8 bytes) into swizzled row: row stride 128B,
// 16B chunks XOR-swizzled by (row & 7).
__device__ __forceinline__ void st4h(char* buf, int r, int c4, float4 v) {
    const uint32_t off =
        (uint32_t)r * 128 + ((((c4 >> 1) ^ (r & 7)) << 4) | ((c4 & 1) << 3));
    __half2* p = (__half2*)(buf + off);
    p[0] = __floats2half2_rn(v.x, v.y);
    p[1] = __floats2half2_rn(v.z, v.w);
}

// ===========================================================================
// SGEMM (fp32): 128x128 tile, 8x8 micro (unchanged)
// ===========================================================================
__global__ __launch_bounds__(256, 2)
void sgemm128(const float* __restrict__ A,
              const float* __restrict__ Bm,
              const float* __restrict__ bias,
              float* __restrict__ Cm,
              int M, int N, int K) {
    __shared__ float As[16][132];
    __shared__ float Bs[16][132];

    const int tid = threadIdx.x;
    const int tx = tid & 15;
    const int ty = tid >> 4;
    const int m0 = blockIdx.y * 128;
    const int n0 = blockIdx.x * 128;

    float acc[8][8] = {};

    for (int k0 = 0; k0 < K; k0 += 16) {
        #pragma unroll
        for (int i = 0; i < 2; i++) {
            const int idx = tid + i * 256;
            const int row = idx >> 2;
            const int c4  = idx & 3;
            float4 a = *(const float4*)&A[(size_t)(m0 + row) * K + k0 + c4 * 4];
            As[c4 * 4 + 0][row] = a.x;
            As[c4 * 4 + 1][row] = a.y;
            As[c4 * 4 + 2][row] = a.z;
            As[c4 * 4 + 3][row] = a.w;
        }
        #pragma unroll
        for (int i = 0; i < 2; i++) {
            const int idx = tid + i * 256;
            const int br  = idx >> 5;
            const int bc4 = idx & 31;
            *(float4*)&Bs[br][bc4 * 4] =
                *(const float4*)&Bm[(size_t)(k0 + br) * N + n0 + bc4 * 4];
        }
        __syncthreads();

        #pragma unroll
        for (int kk = 0; kk < 16; kk++) {
            float av[8], bv[8];
            float4 a0 = *(const float4*)&As[kk][ty * 8];
            float4 a1 = *(const float4*)&As[kk][ty * 8 + 4];
            float4 b0 = *(const float4*)&Bs[kk][tx * 8];
            float4 b1 = *(const float4*)&Bs[kk][tx * 8 + 4];
            av[0]=a0.x; av[1]=a0.y; av[2]=a0.z; av[3]=a0.w;
            av[4]=a1.x; av[5]=a1.y; av[6]=a1.z; av[7]=a1.w;
            bv[0]=b0.x; bv[1]=b0.y; bv[2]=b0.z; bv[3]=b0.w;
            bv[4]=b1.x; bv[5]=b1.y; bv[6]=b1.z; bv[7]=b1.w;
            #pragma unroll
            for (int i = 0; i < 8; i++)
                #pragma unroll
                for (int j = 0; j < 8; j++)
                    acc[i][j] += av[i] * bv[j];
        }
        __syncthreads();
    }

    float4 bb0 = *(const float4*)&bias[n0 + tx * 8];
    float4 bb1 = *(const float4*)&bias[n0 + tx * 8 + 4];
    float bv[8] = {bb0.x, bb0.y, bb0.z, bb0.w, bb1.x, bb1.y, bb1.z, bb1.w};
    #pragma unroll
    for (int i = 0; i < 8; i++) {
        float4 o0, o1;
        o0.x = acc[i][0] + bv[0]; o0.y = acc[i][1] + bv[1];
        o0.z = acc[i][2] + bv[2]; o0.w = acc[i][3] + bv[3];
        o1.x = acc[i][4] + bv[4]; o1.y = acc[i][5] + bv[5];
        o1.z = acc[i][6] + bv[6]; o1.w = acc[i][7] + bv[7];
        float* cp = &Cm[(size_t)(m0 + ty * 8 + i) * N + n0 + tx * 8];
        *(float4*)cp = o0;
        *(float4*)(cp + 4) = o1;
    }
}

// ===========================================================================
// RoPE + split (unchanged)
// ===========================================================================
__global__ void rope_split_kernel(const float* __restrict__ qkv) {
    const int idx = blockIdx.x * blockDim.x + threadIdx.x;
    const int d2 = idx & 31;
    const int h  = (idx >> 5) & 15;
    const int t  = (idx >> 9) & 2047;
    const int b  = idx >> 20;

    const float* base = qkv + (size_t)(b * Tsz + t) * (3 * Csz);
    const int off = h * HDd + d2;

    const float qf = base[off],           qs = base[off + 32];
    const float kf = base[Csz + off],     ks = base[Csz + off + 32];
    const float vf = base[2 * Csz + off], vs = base[2 * Csz + off + 32];

    const float inv_ts = powf(10000.0f, -(float)d2 * (1.0f / 32.0f));
    const float ang = (float)t * inv_ts;
    float sn, cs;
    sincosf(ang, &sn, &cs);

    const size_t o = (size_t)((b * Hn + h) * Tsz + t) * HDd + d2;
    g_q[o]      = qf * cs - qs * sn;
    g_q[o + 32] = qs * cs + qf * sn;
    g_k[o]      = kf * cs - ks * sn;
    g_k[o + 32] = ks * cs + kf * sn;
    g_v[o]      = vf;
    g_v[o + 32] = vs;
}

// ===========================================================================
// Flash attention via mma.sync (fp16 in, fp32 accum), FA2 layout.
// 256 threads / 8 warps; Q tile 128 rows (16/warp), KV tile 64.
// Smem: Q[128][64]h swizzled, K/V double-buffered [64][64]h swizzled.
// ===========================================================================
#define SCALE_L2E 0.1803368801111244f   // 0.125 * log2(e)

__global__ __launch_bounds__(256, 2)
void flash_mma(const float* __restrict__ Q,
               const float* __restrict__ K,
               const float* __restrict__ V,
               float* __restrict__ Y) {
    __shared__ char smem[49152];
    char* Qs = smem;                              // 16 KB
    char* Kb0 = smem + 16384;                     // 8 KB each
    char* Kb1 = smem + 24576;
    char* Vb0 = smem + 32768;
    char* Vb1 = smem + 40960;

    const int tid  = threadIdx.x;
    const int wid  = tid >> 5;
    const int lane = tid & 31;
    const int g = lane >> 2;       // row-in-group
    const int t = lane & 3;        // col pair selector

    const int qt = gridDim.x - 1 - blockIdx.x;    // long blocks first
    const int h  = blockIdx.y;
    const int b  = blockIdx.z;
    const size_t bh = (size_t)(b * Hn + h) * Tsz;
    const int qbase = qt * 128 + wid * 16;
    const int row_lo = qbase + g;
    const int row_hi = row_lo + 8;

    // --- Load Q tile -> fp16 swizzled smem ---
    #pragma unroll
    for (int i = 0; i < 8; i++) {
        const int idx = tid + i * 256;
        const int r  = idx >> 4;
        const int c4 = idx & 15;
        float4 q = *(const float4*)&Q[(bh + qt * 128 + r) * HDd + c4 * 4];
        st4h(Qs, r, c4, q);
    }
    // --- Preload K/V tile 0 ---
    #pragma unroll
    for (int i = 0; i < 4; i++) {
        const int idx = tid + i * 256;
        const int r  = idx >> 4;
        const int c4 = idx & 15;
        float4 kk = *(const float4*)&K[(bh + r) * HDd + c4 * 4];
        st4h(Kb0, r, c4, kk);
        float4 vv = *(const float4*)&V[(bh + r) * HDd + c4 * 4];
        st4h(Vb0, r, c4, vv);
    }
    __syncthreads();

    // --- Q fragments (persistent in registers): qf[ktile][4] ---
    uint32_t qf[4][4];
    {
        const uint32_t sQ = smem_u32(Qs);
        const int mat = lane >> 3;
        const int qr  = wid * 16 + (lane & 7) + ((mat & 1) << 3);
        #pragma unroll
        for (int k = 0; k < 4; k++) {
            const int chunk = 2 * k + (mat >> 1);
            const uint32_t ad = sQ + qr * 128 + (((chunk ^ (qr & 7))) << 4);
            LDSM4(qf[k][0], qf[k][1], qf[k][2], qf[k][3], ad);
        }
    }

    float oacc[8][4] = {};
    float mst[2] = {-1e30f, -1e30f};
    float lst[2] = {0.0f, 0.0f};

    const int nkt = 2 * qt + 2;
    for (int kt = 0; kt < nkt; kt++) {
        char* Kc = (kt & 1) ? Kb1 : Kb0;
        char* Vc = (kt & 1) ? Vb1 : Vb0;

        // Prefetch next K/V into the other buffer
        if (kt + 1 < nkt) {
            char* Kn = (kt & 1) ? Kb0 : Kb1;
            char* Vn = (kt & 1) ? Vb0 : Vb1;
            const size_t base = bh + (size_t)(kt + 1) * 64;
            #pragma unroll
            for (int i = 0; i < 4; i++) {
                const int idx = tid + i * 256;
                const int r  = idx >> 4;
                const int c4 = idx & 15;
                float4 kk = *(const float4*)&K[(base + r) * HDd + c4 * 4];
                st4h(Kn, r, c4, kk);
                float4 vv = *(const float4*)&V[(base + r) * HDd + c4 * 4];
                st4h(Vn, r, c4, vv);
            }
        }

        // --- GEMM1: S = Q @ K^T ---
        float sacc[8][4] = {};
        {
            const uint32_t sK = smem_u32(Kc);
            const int kr = lane & 7;
            #pragma unroll
            for (int n = 0; n < 8; n++) {
                const int row = n * 8 + kr;
                const int c0  = lane >> 3;
                uint32_t kb[8];
                const uint32_t rb = sK + row * 128;
                LDSM4(kb[0], kb[1], kb[2], kb[3],
                      rb + (((c0 ^ (row & 7))) << 4));
                LDSM4(kb[4], kb[5], kb[6], kb[7],
                      rb + ((((c0 + 4) ^ (row & 7))) << 4));
                #pragma unroll
                for (int k = 0; k < 4; k++)
                    MMA16816(sacc[n], qf[k], kb[2 * k], kb[2 * k + 1]);
            }
        }

        // --- Softmax (scale to log2 domain, mask, online update) ---
        const bool dotest = (kt * 64 + 63) > qbase;
        float rmx_lo = -1e30f, rmx_hi = -1e30f;
        #pragma unroll
        for (int n = 0; n < 8; n++) {
            #pragma unroll
            for (int j = 0; j < 4; j++) sacc[n][j] *= SCALE_L2E;
            if (dotest) {
                const int cb = kt * 64 + n * 8 + 2 * t;
                if (cb     > row_lo) sacc[n][0] = -1e30f;
                if (cb + 1 > row_lo) sacc[n][1] = -1e30f;
                if (cb     > row_hi) sacc[n][2] = -1e30f;
                if (cb + 1 > row_hi) sacc[n][3] = -1e30f;
            }
            rmx_lo = fmaxf(rmx_lo, fmaxf(sacc[n][0], sacc[n][1]));
            rmx_hi = fmaxf(rmx_hi, fmaxf(sacc[n][2], sacc[n][3]));
        }
        rmx_lo = fmaxf(rmx_lo, __shfl_xor_sync(0xffffffffu, rmx_lo, 1));
        rmx_lo = fmaxf(rmx_lo, __shfl_xor_sync(0xffffffffu, rmx_lo, 2));
        rmx_hi = fmaxf(rmx_hi, __shfl_xor_sync(0xffffffffu, rmx_hi, 1));
        rmx_hi = fmaxf(rmx_hi, __shfl_xor_sync(0xffffffffu, rmx_hi, 2));

        const float mn_lo = fmaxf(mst[0], rmx_lo);
        const float mn_hi = fmaxf(mst[1], rmx_hi);
        const float corr_lo = ex2f(mst[0] - mn_lo);
        const float corr_hi = ex2f(mst[1] - mn_hi);
        mst[0] = mn_lo; mst[1] = mn_hi;

        float sum_lo = 0.0f, sum_hi = 0.0f;
        #pragma unroll
        for (int n = 0; n < 8; n++) {
            sacc[n][0] = ex2f(sacc[n][0] - mn_lo);
            sacc[n][1] = ex2f(sacc[n][1] - mn_lo);
            sacc[n][2] = ex2f(sacc[n][2] - mn_hi);
            sacc[n][3] = ex2f(sacc[n][3] - mn_hi);
            sum_lo += sacc[n][0] + sacc[n][1];
            sum_hi += sacc[n][2] + sacc[n][3];
        }
        sum_lo += __shfl_xor_sync(0xffffffffu, sum_lo, 1);
        sum_lo += __shfl_xor_sync(0xffffffffu, sum_lo, 2);
        sum_hi += __shfl_xor_sync(0xffffffffu, sum_hi, 1);
        sum_hi += __shfl_xor_sync(0xffffffffu, sum_hi, 2);
        lst[0] = lst[0] * corr_lo + sum_lo;
        lst[1] = lst[1] * corr_hi + sum_hi;

        #pragma unroll
        for (int n = 0; n < 8; n++) {
            oacc[n][0] *= corr_lo; oacc[n][1] *= corr_lo;
            oacc[n][2] *= corr_hi; oacc[n][3] *= corr_hi;
        }

        // --- Pack P accumulators -> A fragments ---
        uint32_t pf[4][4];
        #pragma unroll
        for (int k = 0; k < 4; k++) {
            pf[k][0] = packh2(sacc[2 * k][1],     sacc[2 * k][0]);
            pf[k][1] = packh2(sacc[2 * k][3],     sacc[2 * k][2]);
            pf[k][2] = packh2(sacc[2 * k + 1][1], sacc[2 * k + 1][0]);
            pf[k][3] = packh2(sacc[2 * k + 1][3], sacc[2 * k + 1][2]);
        }

        // --- GEMM2: O += P @ V ---
        {
            const uint32_t sV = smem_u32(Vc);
            const int vr  = (lane >> 3) * 8 + (lane & 7);   // kv row 0..31
            const int vr2 = vr + 32;
            #pragma unroll
            for (int n = 0; n < 8; n++) {
                uint32_t vb[8];
                LDSM4T(vb[0], vb[1], vb[2], vb[3],
                       sV + vr * 128 + (((n ^ (vr & 7))) << 4));
                LDSM4T(vb[4], vb[5], vb[6], vb[7],
                       sV + vr2 * 128 + (((n ^ (vr2 & 7))) << 4));
                #pragma unroll
                for (int k = 0; k < 4; k++)
                    MMA16816(oacc[n], pf[k], vb[2 * k], vb[2 * k + 1]);
            }
        }
        __syncthreads();
    }

    // --- Epilogue: normalize, write [B,T,C] ---
    const float inv_lo = 1.0f / lst[0];
    const float inv_hi = 1.0f / lst[1];
    #pragma unroll
    for (int n = 0; n < 8; n++) {
        const int col = h * HDd + n * 8 + 2 * t;
        float2 o0, o1;
        o0.x = oacc[n][0] * inv_lo; o0.y = oacc[n][1] * inv_lo;
        o1.x = oacc[n][2] * inv_hi; o1.y = oacc[n][3] * inv_hi;
        *(float2*)&Y[((size_t)(b * Tsz) + row_lo) * Csz + col] = o0;
        *(float2*)&Y[((size_t)(b * Tsz) + row_hi) * Csz + col] = o1;
    }
}

// ===========================================================================
extern "C" void kernel_launch(void* const* d_in, const int* in_sizes, int n_in,
                              void* d_out, int out_size) {
    (void)in_sizes; (void)n_in; (void)out_size;
    const float* x      = (const float*)d_in[0];
    const float* w_attn = (const float*)d_in[1];
    const float* b_attn = (const float*)d_in[2];
    const float* w_proj = (const float*)d_in[3];
    const float* b_proj = (const float*)d_in[4];
    float* out = (float*)d_out;

    float *p_qkv, *p_q, *p_k, *p_v, *p_y;
    cudaGetSymbolAddress((void**)&p_qkv, g_qkv);
    cudaGetSymbolAddress((void**)&p_q,   g_q);
    cudaGetSymbolAddress((void**)&p_k,   g_k);
    cudaGetSymbolAddress((void**)&p_v,   g_v);
    cudaGetSymbolAddress((void**)&p_y,   g_y);

    const int M = Bsz * Tsz;

    sgemm128<<<dim3(3 * Csz / 128, M / 128), 256>>>(
        x, w_attn, b_attn, p_qkv, M, 3 * Csz, Csz);

    rope_split_kernel<<<(Bsz * Tsz * Hn * 32) / 256, 256>>>(p_qkv);

    flash_mma<<<dim3(Tsz / 128, Hn, Bsz), 256>>>(p_q, p_k, p_v, p_y);

    sgemm128<<<dim3(Csz / 128, M / 128), 256>>>(
        p_y, w_proj, b_proj, out, M, Csz, Csz);
}